// round 8
// baseline (speedup 1.0000x reference)
#include <cuda_runtime.h>
#include <cuda_fp16.h>
#include <math.h>
#include <stdint.h>

#define BB 4
#define SEQ 8192
#define DIM 256
#define NH 8
#define HD 32
#define INTERNAL 256
#define QKVO 1024
#define KK 512                      // split K (2 x 256)
#define SCALE_F 0.17677669529663687f
#define S_CONST 0.00464534038f

// ---------------- scratch ----------------
__device__ __align__(16) float g_qkvo[(size_t)BB * SEQ * QKVO];      // 128 MB
__device__ __align__(16) __half g_xs[(size_t)BB * SEQ * KK];         // 32 MB
__device__ __align__(16) __half g_ws[(size_t)QKVO * KK];             // 1 MB
__device__ __align__(16) __half g_tmph[(size_t)BB * SEQ * KK];       // 32 MB
__device__ __align__(16) __half g_wp[(size_t)DIM * KK];              // 256 KB
__device__ float g_kv[BB * NH * HD * HD];
__device__ float g_km[BB * NH * HD];
__device__ float g_vm[BB * NH * HD];

__device__ __forceinline__ float elu1(float x) { return x > 0.f ? x + 1.f : __expf(x); }

__device__ __forceinline__ uint32_t smem_u32(const void* p) {
    return (uint32_t)__cvta_generic_to_shared(p);
}
__device__ __forceinline__ void cpa16(uint32_t dst, const void* src) {
    asm volatile("cp.async.cg.shared.global [%0], [%1], 16;" :: "r"(dst), "l"(src));
}
__device__ __forceinline__ void cpa_commit() {
    asm volatile("cp.async.commit_group;" ::: "memory");
}
template <int N> __device__ __forceinline__ void cpa_wait() {
    asm volatile("cp.async.wait_group %0;" :: "n"(N) : "memory");
}
#define LDSM4(r, a) \
    asm volatile("ldmatrix.sync.aligned.m8n8.x4.shared.b16 {%0,%1,%2,%3}, [%4];" \
                 : "=r"((r)[0]), "=r"((r)[1]), "=r"((r)[2]), "=r"((r)[3]) : "r"(a))
#define MMA16816(d, a, b0, b1) \
    asm volatile("mma.sync.aligned.m16n8k16.row.col.f32.f16.f16.f32 " \
                 "{%0,%1,%2,%3},{%4,%5,%6,%7},{%8,%9},{%0,%1,%2,%3};" \
                 : "+f"((d)[0]), "+f"((d)[1]), "+f"((d)[2]), "+f"((d)[3]) \
                 : "r"((a)[0]), "r"((a)[1]), "r"((a)[2]), "r"((a)[3]), "r"(b0), "r"(b1))

// ---------------- GEMM config: 128x128 CTA, warp tile 32x64, 2 CTAs/SM ----------------
#define BM 128
#define BN 128
#define BK 64
#define NCH (KK / BK)               // 8
#define NSTG 3
#define TILEA (BM * 128)            // 16384 B
#define TILEB (BN * 128)            // 16384 B
#define STGB (TILEA + TILEB)        // 32768 B
#define GEMM_SMEM (NSTG * STGB)     // 98304 B

__device__ __forceinline__ void stage_tiles(uint32_t sb, const __half* Ab,
                                            const __half* Bb, int tid,
                                            int chunk, int buf) {
    const uint32_t ab = sb + buf * STGB;
    const uint32_t bbse = ab + TILEA;
    const __half* Ap = Ab + chunk * BK;
    const __half* Bp = Bb + chunk * BK;
#pragma unroll
    for (int i = 0; i < 4; i++) {
        int line = tid + i * 256;            // 0..1023
        int row = line >> 3, j = line & 7;
        uint32_t sw = row * 128 + ((j ^ (row & 7)) << 4);
        cpa16(ab + sw, Ap + (size_t)row * KK + j * 8);
    }
#pragma unroll
    for (int i = 0; i < 4; i++) {
        int line = tid + i * 256;
        int row = line >> 3, j = line & 7;
        uint32_t sw = row * 128 + ((j ^ (row & 7)) << 4);
        cpa16(bbse + sw, Bp + (size_t)row * KK + j * 8);
    }
    cpa_commit();
}

// C[M,Nn] = A'[M,512]h @ B'[Nn,512]h^T + bias (fp32 accum)
__global__ __launch_bounds__(256, 2)
void gemm_half(const __half* __restrict__ A, const __half* __restrict__ Bm,
               const float* __restrict__ bias, float* __restrict__ C, int Nn) {
    extern __shared__ char smem[];
    const uint32_t sb = smem_u32(smem);
    const int tid = threadIdx.x;
    const int wid = tid >> 5;
    const int lane = tid & 31;
    const int bm = blockIdx.y * BM;
    const int bn = blockIdx.x * BN;
    const int wm0 = (wid & 3) * 32;          // 4 warps in M
    const int wn0 = (wid >> 2) * 64;         // 2 warps in N

    const __half* Ab = A + (size_t)bm * KK;
    const __half* Bb = Bm + (size_t)bn * KK;

    float acc[2][8][4];
#pragma unroll
    for (int i = 0; i < 2; i++)
#pragma unroll
        for (int j = 0; j < 8; j++)
#pragma unroll
            for (int k = 0; k < 4; k++) acc[i][j][k] = 0.f;

    const int lrA = (lane & 7) + ((lane >> 3) & 1) * 8;
    const int lcA = ((lane >> 4) & 1) * 16;
    const int lrB = ((lane >> 4) & 1) * 8 + (lane & 7);
    const int lcB = ((lane >> 3) & 1) * 16;

    stage_tiles(sb, Ab, Bb, tid, 0, 0);
    stage_tiles(sb, Ab, Bb, tid, 1, 1);

    for (int c = 0; c < NCH; c++) {
        if (c + 2 < NCH) cpa_wait<1>(); else cpa_wait<0>();
        __syncthreads();
        if (c + 2 < NCH) stage_tiles(sb, Ab, Bb, tid, c + 2, (c + 2) % NSTG);
        const uint32_t ab = sb + (c % NSTG) * STGB;
        const uint32_t bbse = ab + TILEA;
#pragma unroll
        for (int ks = 0; ks < 4; ks++) {
            uint32_t afr[2][4], bfr[4][4];
#pragma unroll
            for (int mi = 0; mi < 2; mi++) {
                int r = wm0 + mi * 16 + lrA;
                uint32_t cc = (uint32_t)(ks * 32 + lcA);
                LDSM4(afr[mi], ab + r * 128 + (cc ^ ((r & 7) << 4)));
            }
#pragma unroll
            for (int bi = 0; bi < 4; bi++) {
                int r = wn0 + bi * 16 + lrB;
                uint32_t cc = (uint32_t)(ks * 32 + lcB);
                LDSM4(bfr[bi], bbse + r * 128 + (cc ^ ((r & 7) << 4)));
            }
#pragma unroll
            for (int mi = 0; mi < 2; mi++)
#pragma unroll
                for (int nj = 0; nj < 8; nj++)
                    MMA16816(acc[mi][nj], afr[mi],
                             bfr[nj >> 1][(nj & 1) * 2], bfr[nj >> 1][(nj & 1) * 2 + 1]);
        }
    }

    const int g = lane >> 2, t4 = lane & 3;
#pragma unroll
    for (int mi = 0; mi < 2; mi++) {
#pragma unroll
        for (int nj = 0; nj < 8; nj++) {
            const int col = bn + wn0 + nj * 8 + t4 * 2;
            const float2 bv = *(const float2*)(bias + col);
            const int row0 = bm + wm0 + mi * 16 + g;
            float2 o0 = {acc[mi][nj][0] + bv.x, acc[mi][nj][1] + bv.y};
            float2 o1 = {acc[mi][nj][2] + bv.x, acc[mi][nj][3] + bv.y};
            *(float2*)(C + (size_t)row0 * Nn + col) = o0;
            *(float2*)(C + (size_t)(row0 + 8) * Nn + col) = o1;
        }
    }
}

// ---------------- fused prep: all splits + accumulator zeroing, one launch ----------------
#define TX (BB * SEQ * DIM)         // 8388608
#define TW (QKVO * DIM)             // 262144
#define TP (DIM * DIM)              // 65536
#define NKV (BB * NH * HD * HD)     // 32768
#define NKM (BB * NH * HD)          // 1024
#define TTOT (TX + TW + TP + NKV + 2 * NKM)

__global__ void prep_kernel(const float* __restrict__ x,
                            const float* __restrict__ W_qkvo,
                            const float* __restrict__ W_proj) {
    int i = blockIdx.x * 256 + threadIdx.x;
    if (i >= TTOT) return;
    if (i < TX) {
        int row = i >> 8, c = i & 255;
        float v = x[i];
        __half hi = __float2half_rn(v);
        __half lo = __float2half_rn(v - __half2float(hi));
        size_t base = (size_t)row * KK + c;
        g_xs[base] = hi;
        g_xs[base + 256] = lo;               // A operand: [hi | lo]
    } else if (i < TX + TW) {
        int k = i - TX;
        int row = k >> 8, c = k & 255;
        float v = W_qkvo[k];
        __half hi = __float2half_rn(v);
        size_t base = (size_t)row * KK + c;
        g_ws[base] = hi;
        g_ws[base + 256] = hi;               // B operand: [hi | hi]
    } else if (i < TX + TW + TP) {
        int k = i - TX - TW;
        int row = k >> 8, c = k & 255;
        float v = W_proj[k];
        __half hi = __float2half_rn(v);
        size_t base = (size_t)row * KK + c;
        g_wp[base] = hi;
        g_wp[base + 256] = hi;
    } else {
        int k = i - TX - TW - TP;
        if (k < NKV) g_kv[k] = 0.f;
        else if (k < NKV + NKM) g_km[k - NKV] = 0.f;
        else g_vm[k - NKV - NKM] = 0.f;
    }
}

// ---------------- per-(b,h) state reduction: double-buffered, 1 sync / 8 tokens ----------
#define CHUNK 512
#define NIT (CHUNK / 8)
__global__ __launch_bounds__(256)
void reduce_kernel(const float* __restrict__ sinp, const float* __restrict__ cosp) {
    const int bh = blockIdx.x;
    const int chunk = blockIdx.y;
    const int b = bh / NH, h = bh % NH;
    const int tid = threadIdx.x;
    const int j = tid >> 5;                  // token sub 0..7
    const int d = tid & 31;
    const int dbase = j * 4;
    __shared__ float s_ks[2][8][32];
    __shared__ float s_vs[2][8][32];
    float acc[4] = {0.f, 0.f, 0.f, 0.f};
    float ksum = 0.f, vsum = 0.f;
    const int n0 = chunk * CHUNK;
    const float sgn = (d & 1) ? 1.f : -1.f;
    const size_t kcol = INTERNAL + h * HD;
    const size_t vcol = 2 * INTERNAL + h * HD;

    {
        const int n = n0 + j;
        const size_t row = ((size_t)b * SEQ + n) * QKVO;
        const float kh  = elu1(g_qkvo[row + kcol + d]);
        const float khp = elu1(g_qkvo[row + kcol + (d ^ 1)]);
        const float vv  = g_qkvo[row + vcol + d];
        const float sn = sinp[n * HD + d];
        const float cs = cosp[n * HD + d];
        s_ks[0][j][d] = (kh * cs + sgn * khp * sn) * S_CONST;
        s_vs[0][j][d] = vv * S_CONST;
        ksum += kh;
        vsum += vv;
    }
    __syncthreads();

    for (int it = 0; it < NIT; it++) {
        const int bsel = it & 1;
        float nk = 0.f, nkp = 0.f, nv = 0.f, nsn = 0.f, ncs = 0.f;
        const bool more = (it + 1 < NIT);
        if (more) {
            const int n = n0 + (it + 1) * 8 + j;
            const size_t row = ((size_t)b * SEQ + n) * QKVO;
            nk  = g_qkvo[row + kcol + d];
            nkp = g_qkvo[row + kcol + (d ^ 1)];
            nv  = g_qkvo[row + vcol + d];
            nsn = sinp[n * HD + d];
            ncs = cosp[n * HD + d];
        }
#pragma unroll
        for (int jj = 0; jj < 8; jj++) {
            const float vv = s_vs[bsel][jj][d];
#pragma unroll
            for (int dd = 0; dd < 4; dd++)
                acc[dd] += s_ks[bsel][jj][dbase + dd] * vv;
        }
        if (more) {
            const float kh = elu1(nk);
            const float khp = elu1(nkp);
            s_ks[bsel ^ 1][j][d] = (kh * ncs + sgn * khp * nsn) * S_CONST;
            s_vs[bsel ^ 1][j][d] = nv * S_CONST;
            ksum += kh;
            vsum += nv;
        }
        __syncthreads();
    }
#pragma unroll
    for (int dd = 0; dd < 4; dd++)
        atomicAdd(&g_kv[(bh * HD + dbase + dd) * HD + d], acc[dd]);
    atomicAdd(&g_km[bh * HD + d], ksum);
    atomicAdd(&g_vm[bh * HD + d], vsum);
}

// ---------------- attn epilogue: 8 lanes per token (coalesced head rows) ----------------
// block: 512 threads = 64 tokens; warp = 4 tokens x 8 lanes
#define ATOK 64
__global__ __launch_bounds__(512)
void attn_kernel(const float* __restrict__ sinp, const float* __restrict__ cosp,
                 const float* __restrict__ W_lepe, const float* __restrict__ b_lepe) {
    const int b = blockIdx.y;
    const int h = blockIdx.z;
    const int bh = b * NH + h;
    const int tid = threadIdx.x;
    const int lane = tid & 31;
    const int slot = lane & 7;               // float4 slot within head row
    const int n = blockIdx.x * ATOK + (tid >> 3);  // token
    const int d0 = slot * 4;                 // this lane's 4 channels

    __shared__ __align__(16) float s_kv[HD][HD];
    __shared__ float s_km[HD], s_vm[HD], s_w0[HD], s_w1[HD], s_w2[HD], s_bl[HD];

    for (int i = tid; i < HD * HD; i += 512)
        ((float*)s_kv)[i] = g_kv[bh * HD * HD + i];
    if (tid < HD) {
        const int c = h * HD + tid;
        const float invN = 1.f / (float)SEQ;
        s_km[tid] = g_km[bh * HD + tid] * invN;
        s_vm[tid] = g_vm[bh * HD + tid] * invN;
        s_w0[tid] = W_lepe[c * 3 + 0];
        s_w1[tid] = W_lepe[c * 3 + 1];
        s_w2[tid] = W_lepe[c * 3 + 2];
        s_bl[tid] = b_lepe[c];
    }
    __syncthreads();

    const size_t row = ((size_t)b * SEQ + n) * QKVO;
    const int cb = h * HD;
    const unsigned FM = 0xffffffffu;

    // q slot -> registers, elu+1
    float4 qv = *(const float4*)(g_qkvo + row + cb + d0);
    float q0 = elu1(qv.x), q1 = elu1(qv.y), q2 = elu1(qv.z), q3 = elu1(qv.w);

    // z: partial dot over this lane's 4 channels, reduce across the 8-lane group
    float zv = q0 * s_km[d0] + q1 * s_km[d0 + 1] + q2 * s_km[d0 + 2] + q3 * s_km[d0 + 3];
    zv += __shfl_xor_sync(FM, zv, 1);
    zv += __shfl_xor_sync(FM, zv, 2);
    zv += __shfl_xor_sync(FM, zv, 4);
    const float z = zv * SCALE_F;

    // theta shift (pairs are in-thread: (d0,d0+1), (d0+2,d0+3))
    float4 sn4 = *(const float4*)(sinp + (size_t)n * HD + d0);
    float4 cs4 = *(const float4*)(cosp + (size_t)n * HD + d0);
    float qs0 = q0 * cs4.x - q1 * sn4.x;
    float qs1 = q1 * cs4.y + q0 * sn4.y;
    float qs2 = q2 * cs4.z - q3 * sn4.z;
    float qs3 = q3 * cs4.w + q2 * sn4.w;

    // matvec: acc[e] = sum_d qs[d] * kv[d][e] for this lane's 4 e's
    float a0 = 0.f, a1 = 0.f, a2 = 0.f, a3 = 0.f;
    const int gbase = lane & 24;             // token group base lane
#pragma unroll
    for (int s = 0; s < 8; s++) {
        const int src = gbase | s;
        const float p0 = __shfl_sync(FM, qs0, src);
        const float p1 = __shfl_sync(FM, qs1, src);
        const float p2 = __shfl_sync(FM, qs2, src);
        const float p3 = __shfl_sync(FM, qs3, src);
        const float4 k0 = *(const float4*)(&s_kv[s * 4 + 0][d0]);
        const float4 k1 = *(const float4*)(&s_kv[s * 4 + 1][d0]);
        const float4 k2 = *(const float4*)(&s_kv[s * 4 + 2][d0]);
        const float4 k3 = *(const float4*)(&s_kv[s * 4 + 3][d0]);
        a0 += p0 * k0.x + p1 * k1.x + p2 * k2.x + p3 * k3.x;
        a1 += p0 * k0.y + p1 * k1.y + p2 * k2.y + p3 * k3.y;
        a2 += p0 * k0.z + p1 * k1.z + p2 * k2.z + p3 * k3.z;
        a3 += p0 * k0.w + p1 * k1.w + p2 * k2.w + p3 * k3.w;
    }

    const float zf = 1.f + 1.f / (z + 1e-6f);
    const float4 v0 = *(const float4*)(g_qkvo + row + 2 * INTERNAL + cb + d0);
    const float4 vp = (n > 0) ? *(const float4*)(g_qkvo + row - QKVO + 2 * INTERNAL + cb + d0)
                              : make_float4(0, 0, 0, 0);
    const float4 vn = (n < SEQ - 1) ? *(const float4*)(g_qkvo + row + QKVO + 2 * INTERNAL + cb + d0)
                                    : make_float4(0, 0, 0, 0);
    const float4 og = *(const float4*)(g_qkvo + row + 3 * INTERNAL + cb + d0);

    float r0 = (a0 * zf - z * s_vm[d0 + 0]
                + vp.x * s_w0[d0 + 0] + v0.x * s_w1[d0 + 0] + vn.x * s_w2[d0 + 0] + s_bl[d0 + 0]) * og.x;
    float r1 = (a1 * zf - z * s_vm[d0 + 1]
                + vp.y * s_w0[d0 + 1] + v0.y * s_w1[d0 + 1] + vn.y * s_w2[d0 + 1] + s_bl[d0 + 1]) * og.y;
    float r2 = (a2 * zf - z * s_vm[d0 + 2]
                + vp.z * s_w0[d0 + 2] + v0.z * s_w1[d0 + 2] + vn.z * s_w2[d0 + 2] + s_bl[d0 + 2]) * og.z;
    float r3 = (a3 * zf - z * s_vm[d0 + 3]
                + vp.w * s_w0[d0 + 3] + v0.w * s_w1[d0 + 3] + vn.w * s_w2[d0 + 3] + s_bl[d0 + 3]) * og.w;

    __half h0 = __float2half_rn(r0), h1 = __float2half_rn(r1);
    __half h2 = __float2half_rn(r2), h3 = __float2half_rn(r3);
    __half l0 = __float2half_rn(r0 - __half2float(h0));
    __half l1 = __float2half_rn(r1 - __half2float(h1));
    __half l2 = __float2half_rn(r2 - __half2float(h2));
    __half l3 = __float2half_rn(r3 - __half2float(h3));
    uint2 hw, lw;
    hw.x = ((uint32_t)__half_as_ushort(h1) << 16) | __half_as_ushort(h0);
    hw.y = ((uint32_t)__half_as_ushort(h3) << 16) | __half_as_ushort(h2);
    lw.x = ((uint32_t)__half_as_ushort(l1) << 16) | __half_as_ushort(l0);
    lw.y = ((uint32_t)__half_as_ushort(l3) << 16) | __half_as_ushort(l2);
    __half* outp = g_tmph + ((size_t)b * SEQ + n) * KK + cb + d0;
    *(uint2*)(outp) = hw;
    *(uint2*)(outp + 256) = lw;
}

// ---------------- launch ----------------
extern "C" void kernel_launch(void* const* d_in, const int* in_sizes, int n_in,
                              void* d_out, int out_size) {
    const float* x      = (const float*)d_in[0];
    const float* sinp   = (const float*)d_in[1];
    const float* cosp   = (const float*)d_in[2];
    const float* W_qkvo = (const float*)d_in[3];
    const float* b_qkvo = (const float*)d_in[4];
    const float* W_lepe = (const float*)d_in[5];
    const float* b_lepe = (const float*)d_in[6];
    const float* W_proj = (const float*)d_in[7];
    const float* b_proj = (const float*)d_in[8];
    float* out = (float*)d_out;

    __half *xs_p, *ws_p, *tmph_p, *wp_p;
    float* qkvo_p;
    cudaGetSymbolAddress((void**)&qkvo_p, g_qkvo);
    cudaGetSymbolAddress((void**)&xs_p, g_xs);
    cudaGetSymbolAddress((void**)&ws_p, g_ws);
    cudaGetSymbolAddress((void**)&tmph_p, g_tmph);
    cudaGetSymbolAddress((void**)&wp_p, g_wp);

    cudaFuncSetAttribute(gemm_half, cudaFuncAttributeMaxDynamicSharedMemorySize, GEMM_SMEM);

    const int M = BB * SEQ;  // 32768

    // 0) fused splits + zeroing, one launch
    prep_kernel<<<(TTOT + 255) / 256, 256>>>(x, W_qkvo, W_proj);

    // 1) qkvo = x @ W_qkvo^T + b  (HMMA, K=512 split)
    {
        dim3 grid(QKVO / BN, M / BM);
        gemm_half<<<grid, 256, GEMM_SMEM>>>(xs_p, ws_p, b_qkvo, qkvo_p, QKVO);
    }
    // 2) state reduction
    {
        dim3 grid(BB * NH, SEQ / CHUNK);
        reduce_kernel<<<grid, 256>>>(sinp, cosp);
    }
    // 3) attention epilogue (8 lanes per token)
    {
        dim3 grid(SEQ / ATOK, BB, NH);
        attn_kernel<<<grid, 512>>>(sinp, cosp, W_lepe, b_lepe);
    }
    // 4) out = tmp @ W_proj^T + b_proj  (HMMA)
    {
        dim3 grid(DIM / BN, M / BM);
        gemm_half<<<grid, 256, GEMM_SMEM>>>(tmph_p, wp_p, b_proj, out, DIM);
    }
}